// round 15
// baseline (speedup 1.0000x reference)
#include <cuda_runtime.h>
#include <cstdint>

#define BATCH 4
#define LSEQ 4096
#define DMODEL_ 1024
#define DKH 64
#define MROWS (BATCH*LSEQ)   // 16384
#define NQB 64               // 64-key tiles per batch
#define NQB3 16              // 256-row q-blocks per batch
#define KCHUNK 8             // key tiles per split-K work item
#define MAXCH 8              // max chunks per 256-row q-block
#define NTILES (BATCH*NQB)   // 256 key tiles total

// projected q,v as fp16 (half2 packed in uint32), row-major [row][32 half2]
// q pre-scaled by 0.125*log2(e)
__device__ uint32_t g_q[MROWS*32];
__device__ uint32_t g_v[MROWS*32];

// fp16 B-fragment-ordered weights: [slice 3][kt 64][ntp 4][lane 32] uint4
__device__ uint4 g_wf16[3*8192];

// mma-fragment-ordered K/V tiles (fp16): per tile 512 uint4 (8KB)
__device__ uint4 g_kf[NTILES*512];
__device__ uint4 g_vf[NTILES*512];

// split-K partials (Q >= 2): item = (b*16+Q)*MAXCH + ci
// each item: 256 rows x 64 cols O + 256 l values
__device__ float g_opart[(size_t)BATCH*NQB3*MAXCH*16384];   // 33.5 MB
__device__ float g_lpart[BATCH*NQB3*MAXCH*256];

__device__ __forceinline__ uint32_t packh2(float lo, float hi) {
    uint32_t d;
    asm("cvt.rn.f16x2.f32 %0, %1, %2;" : "=r"(d) : "f"(hi), "f"(lo));
    return d;
}

__device__ __forceinline__ float ex2f(float x) {
    float r;
    asm("ex2.approx.f32 %0, %1;" : "=f"(r) : "f"(x));
    return r;
}

__device__ __forceinline__ void mma_f16(float c[4],
    uint32_t a0, uint32_t a1, uint32_t a2, uint32_t a3,
    uint32_t b0, uint32_t b1)
{
    asm volatile(
        "mma.sync.aligned.m16n8k16.row.col.f32.f16.f16.f32 "
        "{%0,%1,%2,%3}, {%4,%5,%6,%7}, {%8,%9}, {%0,%1,%2,%3};\n"
        : "+f"(c[0]), "+f"(c[1]), "+f"(c[2]), "+f"(c[3])
        : "r"(a0), "r"(a1), "r"(a2), "r"(a3), "r"(b0), "r"(b1));
}

__device__ __forceinline__ void cp16(uint32_t saddr, const void* g) {
    asm volatile("cp.async.cg.shared.global [%0], [%1], 16;" :: "r"(saddr), "l"(g));
}
#define CP_COMMIT() asm volatile("cp.async.commit_group;")
#define CP_WAIT0()  asm volatile("cp.async.wait_group 0;")
#define CP_WAIT2()  asm volatile("cp.async.wait_group 2;")

// ---------------------------------------------------------------------------
// Setup: fp16 fragment-ordered W. (unchanged)
// ---------------------------------------------------------------------------
__global__ void wfrag16_kernel(const float* __restrict__ Wq,
                               const float* __restrict__ Wk,
                               const float* __restrict__ Wv)
{
    int idx = blockIdx.x * 256 + threadIdx.x;
    int slice = idx >> 13;
    int rem = idx & 8191;
    int kt = rem >> 7;
    int ntp = (rem >> 5) & 3;
    int l = rem & 31;
    int g = l >> 2, t = l & 3;
    const float* W = (slice == 0) ? Wq : (slice == 1) ? Wk : Wv;
    int n0 = 2 * ntp * 8 + g;
    int k0 = 16 * kt + 2 * t;
    uint4 v;
    v.x = packh2(W[k0 * DKH + n0],           W[(k0 + 1) * DKH + n0]);
    v.y = packh2(W[(k0 + 8) * DKH + n0],     W[(k0 + 9) * DKH + n0]);
    v.z = packh2(W[k0 * DKH + n0 + 8],       W[(k0 + 1) * DKH + n0 + 8]);
    v.w = packh2(W[(k0 + 8) * DKH + n0 + 8], W[(k0 + 9) * DKH + n0 + 8]);
    g_wf16[idx] = v;
}

// ---------------------------------------------------------------------------
// Projection v3 (unchanged from R13/R14). grid = (128, 1, 3)
// ---------------------------------------------------------------------------
#define P3_XSTRIDE 36
#define P3_XSTAGE_B (128*P3_XSTRIDE*4)
#define P3_WSTAGE_B 4096
#define P3_SMEM_BYTES (4*P3_XSTAGE_B + 4*P3_WSTAGE_B)   // 90112

__global__ __launch_bounds__(256, 2) void proj3_kernel(
    const float* __restrict__ Qin, const float* __restrict__ Kin, const float* __restrict__ Vin,
    const float* __restrict__ bq, const float* __restrict__ bk, const float* __restrict__ bv)
{
    extern __shared__ char smraw[];
    const float* Xs = (const float*)smraw;
    const uint4* Ws = (const uint4*)(smraw + 4 * P3_XSTAGE_B);
    const uint32_t xsb = (uint32_t)__cvta_generic_to_shared(smraw);
    const uint32_t wsb = xsb + 4 * P3_XSTAGE_B;

    const int which = blockIdx.z;
    const float* X    = (which == 0) ? Qin : (which == 1) ? Kin : Vin;
    const float* bias = (which == 0) ? bq  : (which == 1) ? bk  : bv;
    const float scale = (which == 0) ? 0.125f * 1.44269504088896340736f : 1.0f;

    const int tid = threadIdx.x;
    const int w = tid >> 5;
    const int l = tid & 31;
    const int g = l >> 2;
    const int t = l & 3;
    const int row_base = blockIdx.x * 128;
    const float* Xp = X + (size_t)row_base * DMODEL_;
    const uint4* wsrc = g_wf16 + which * 8192;

    float acc[8][4];
    #pragma unroll
    for (int nt = 0; nt < 8; nt++)
        #pragma unroll
        for (int j = 0; j < 4; j++) acc[nt][j] = 0.f;

    auto issue = [&](int ch) {
        if (ch < 32) {
            uint32_t xb = xsb + (uint32_t)(ch & 3) * P3_XSTAGE_B;
            #pragma unroll
            for (int i = 0; i < 4; i++) {
                int f = tid + i * 256;
                int r = f >> 3, c = f & 7;
                cp16(xb + (uint32_t)(r * P3_XSTRIDE + c * 4) * 4,
                     Xp + (size_t)r * DMODEL_ + ch * 32 + c * 4);
            }
            uint32_t wb = wsb + (uint32_t)(ch & 3) * P3_WSTAGE_B;
            cp16(wb + (uint32_t)tid * 16, wsrc + ch * 256 + tid);
        }
        CP_COMMIT();
    };

    issue(0); issue(1); issue(2);

    const int r0 = 16 * w + g;
    for (int ch = 0; ch < 32; ch++) {
        CP_WAIT2();
        __syncthreads();
        issue(ch + 3);

        const float* Xc = Xs + (ch & 3) * (128 * P3_XSTRIDE);
        const uint4* Wc = Ws + (ch & 3) * 256;

        #pragma unroll
        for (int kk = 0; kk < 2; kk++) {
            int cb = kk * 16 + 2 * t;
            float2 q0 = *(const float2*)&Xc[r0 * P3_XSTRIDE + cb];
            float2 q1 = *(const float2*)&Xc[(r0 + 8) * P3_XSTRIDE + cb];
            float2 q2 = *(const float2*)&Xc[r0 * P3_XSTRIDE + cb + 8];
            float2 q3 = *(const float2*)&Xc[(r0 + 8) * P3_XSTRIDE + cb + 8];
            uint32_t a0 = packh2(q0.x, q0.y);
            uint32_t a1 = packh2(q1.x, q1.y);
            uint32_t a2 = packh2(q2.x, q2.y);
            uint32_t a3 = packh2(q3.x, q3.y);
            #pragma unroll
            for (int ntp = 0; ntp < 4; ntp++) {
                uint4 f = Wc[(kk * 4 + ntp) * 32 + l];
                mma_f16(acc[2 * ntp],     a0, a1, a2, a3, f.x, f.y);
                mma_f16(acc[2 * ntp + 1], a0, a1, a2, a3, f.z, f.w);
            }
        }
    }

    if (which == 1) {
        const int T = 2 * blockIdx.x + (w >> 2);
        const int ntp = w & 3;
        #pragma unroll
        for (int kt = 0; kt < 4; kt++) {
            int c0 = (2 * kt) * 8 + 2 * t;
            int c1 = (2 * kt + 1) * 8 + 2 * t;
            float b00 = bias[c0], b01 = bias[c0 + 1];
            float b10 = bias[c1], b11 = bias[c1 + 1];
            uint4 v;
            v.x = packh2(acc[2 * kt][0] + b00,     acc[2 * kt][1] + b01);
            v.y = packh2(acc[2 * kt + 1][0] + b10, acc[2 * kt + 1][1] + b11);
            v.z = packh2(acc[2 * kt][2] + b00,     acc[2 * kt][3] + b01);
            v.w = packh2(acc[2 * kt + 1][2] + b10, acc[2 * kt + 1][3] + b11);
            g_kf[T * 512 + (kt * 4 + ntp) * 32 + l] = v;
        }
    } else {
        uint32_t* Y = (which == 0) ? g_q : g_v;
        #pragma unroll
        for (int nt = 0; nt < 8; nt++) {
            int c = nt * 8 + 2 * t;
            float b0v = bias[c], b1v = bias[c + 1];
            Y[(size_t)(row_base + r0) * 32 + nt * 4 + t] =
                packh2((acc[nt][0] + b0v) * scale, (acc[nt][1] + b1v) * scale);
            Y[(size_t)(row_base + r0 + 8) * 32 + nt * 4 + t] =
                packh2((acc[nt][2] + b0v) * scale, (acc[nt][3] + b1v) * scale);
        }
    }
}

// ---------------------------------------------------------------------------
// Repack V only into PV B-fragment order (unchanged).
// ---------------------------------------------------------------------------
__global__ void repack_kernel()
{
    int idx = blockIdx.x * 256 + threadIdx.x;
    int T = idx >> 9;
    int r = idx & 511;
    int kt = r >> 7;
    int ntp = (r >> 5) & 3;
    int l = r & 31;
    int g = l >> 2, t = l & 3;
    int row0 = T * 64;

    const unsigned short* vh = (const unsigned short*)g_v;

    uint4 vv;
    {
        int kr = row0 + kt * 16;
        int nt = 2 * ntp;
        int col = nt * 8 + g;
        unsigned v0 = vh[(size_t)(kr + 2 * t) * 64 + col];
        unsigned v1 = vh[(size_t)(kr + 2 * t + 1) * 64 + col];
        unsigned v2 = vh[(size_t)(kr + 2 * t + 8) * 64 + col];
        unsigned v3 = vh[(size_t)(kr + 2 * t + 9) * 64 + col];
        vv.x = v0 | (v1 << 16);
        vv.y = v2 | (v3 << 16);
        col += 8;
        v0 = vh[(size_t)(kr + 2 * t) * 64 + col];
        v1 = vh[(size_t)(kr + 2 * t + 1) * 64 + col];
        v2 = vh[(size_t)(kr + 2 * t + 8) * 64 + col];
        v3 = vh[(size_t)(kr + 2 * t + 9) * 64 + col];
        vv.z = v0 | (v1 << 16);
        vv.w = v2 | (v3 << 16);
    }
    g_vf[idx] = vv;
}

// ---------------------------------------------------------------------------
// Attention stage 1: 256-row q-blocks, warp = 32 rows x 64 keys.
// Per-pp (16-key chunk) loop: each K/V fragment LDS feeds BOTH 16-row
// halves -> smem read per 16rx64k unit halved vs R14.
// Early-out for fully-masked warp-tiles. grid = (8 ci, 16 Q, 4 b)
// ---------------------------------------------------------------------------
#define ATT_SMEM_BYTES 32768

__global__ __launch_bounds__(256) void attn_part_kernel(float* __restrict__ out)
{
    extern __shared__ uint4 sm4[];
    const uint32_t smb = (uint32_t)__cvta_generic_to_shared(sm4);

    const int ci = blockIdx.x;
    const int Q  = blockIdx.y;          // 256-row q-block
    const int b  = blockIdx.z;
    const int ntiles = 4 * Q + 4;
    const int kstart = ci * KCHUNK;
    if (kstart >= ntiles) return;
    const int kend = min(kstart + KCHUNK, ntiles);

    const int tid = threadIdx.x;
    const int w = tid >> 5;             // rows 32w..32w+31 of block
    const int l = tid & 31;
    const int g = l >> 2;
    const int t = l & 3;
    const int rowA = 256 * Q + 32 * w;  // global base of A half

    // Q A-frags: A half rows rowA+g/+8, B half rows rowA+16+g/+24
    uint32_t qaA[4][4], qaB[4][4];
    {
        const uint32_t* qu = g_q + ((size_t)b * LSEQ + rowA + g) * 32;
        #pragma unroll
        for (int kt = 0; kt < 4; kt++) {
            qaA[kt][0] = qu[kt * 8 + t];
            qaA[kt][1] = qu[8 * 32 + kt * 8 + t];
            qaA[kt][2] = qu[kt * 8 + t + 4];
            qaA[kt][3] = qu[8 * 32 + kt * 8 + t + 4];
            qaB[kt][0] = qu[16 * 32 + kt * 8 + t];
            qaB[kt][1] = qu[24 * 32 + kt * 8 + t];
            qaB[kt][2] = qu[16 * 32 + kt * 8 + t + 4];
            qaB[kt][3] = qu[24 * 32 + kt * 8 + t + 4];
        }
    }

    float oA[8][4], oB[8][4];
    #pragma unroll
    for (int nt = 0; nt < 8; nt++)
        #pragma unroll
        for (int j = 0; j < 4; j++) { oA[nt][j] = 0.f; oB[nt][j] = 0.f; }
    float lfA[4] = {0.f, 0.f, 0.f, 0.f};
    float lfB[4] = {0.f, 0.f, 0.f, 0.f};
    const uint32_t ONES = 0x3C003C00u;

    auto stage = [&](int kb, int p) {
        const uint4* kp = g_kf + (size_t)(b * NQB + kb) * 512;
        const uint4* vp = g_vf + (size_t)(b * NQB + kb) * 512;
        uint32_t kd = smb + (uint32_t)p * 8192;
        uint32_t vd = smb + 16384u + (uint32_t)p * 8192;
        #pragma unroll
        for (int i = 0; i < 2; i++) {
            int u = tid + i * 256;
            cp16(kd + (uint32_t)u * 16, kp + u);
            cp16(vd + (uint32_t)u * 16, vp + u);
        }
        CP_COMMIT();
    };

    stage(kstart, 0);

    for (int kb = kstart; kb < kend; kb++) {
        const int p = (kb - kstart) & 1;
        CP_WAIT0();
        __syncthreads();
        const uint4* Kc = sm4 + p * 512;
        const uint4* Vc = sm4 + 1024 + p * 512;

        if (kb + 1 < kend) stage(kb + 1, 1 - p);

        // early-out: tile fully masked for this warp's 32 rows
        if (64 * kb >= rowA - 256 * Q + 256 * Q + 32) {
            // i.e. 64*kb >= 32*w + 32 relative? compute properly below
        }
        const int dbase = 64 * kb - rowA;       // key offset - row base
        if (dbase >= 32) continue;              // all keys > all rows

        #pragma unroll
        for (int pp = 0; pp < 4; pp++) {
            // load K fragment column once, use for both halves
            uint4 kf0 = Kc[(0 * 4 + pp) * 32 + l];
            uint4 kf1 = Kc[(1 * 4 + pp) * 32 + l];
            uint4 kf2 = Kc[(2 * 4 + pp) * 32 + l];
            uint4 kf3 = Kc[(3 * 4 + pp) * 32 + l];

            float sA[2][4] = {}, sB[2][4] = {};
            mma_f16(sA[0], qaA[0][0], qaA[0][1], qaA[0][2], qaA[0][3], kf0.x, kf0.y);
            mma_f16(sA[1], qaA[0][0], qaA[0][1], qaA[0][2], qaA[0][3], kf0.z, kf0.w);
            mma_f16(sB[0], qaB[0][0], qaB[0][1], qaB[0][2], qaB[0][3], kf0.x, kf0.y);
            mma_f16(sB[1], qaB[0][0], qaB[0][1], qaB[0][2], qaB[0][3], kf0.z, kf0.w);
            mma_f16(sA[0], qaA[1][0], qaA[1][1], qaA[1][2], qaA[1][3], kf1.x, kf1.y);
            mma_f16(sA[1], qaA[1][0], qaA[1][1], qaA[1][2], qaA[1][3], kf1.z, kf1.w);
            mma_f16(sB[0], qaB[1][0], qaB[1][1], qaB[1][2], qaB[1][3], kf1.x, kf1.y);
            mma_f16(sB[1], qaB[1][0], qaB[1][1], qaB[1][2], qaB[1][3], kf1.z, kf1.w);
            mma_f16(sA[0], qaA[2][0], qaA[2][1], qaA[2][2], qaA[2][3], kf2.x, kf2.y);
            mma_f16(sA[1], qaA[2][0], qaA[2][1], qaA[2][2], qaA[2][3], kf2.z, kf2.w);
            mma_f16(sB[0], qaB[2][0], qaB[2][1], qaB[2][2], qaB[2][3], kf2.x, kf2.y);
            mma_f16(sB[1], qaB[2][0], qaB[2][1], qaB[2][2], qaB[2][3], kf2.z, kf2.w);
            mma_f16(sA[0], qaA[3][0], qaA[3][1], qaA[3][2], qaA[3][3], kf3.x, kf3.y);
            mma_f16(sA[1], qaA[3][0], qaA[3][1], qaA[3][2], qaA[3][3], kf3.z, kf3.w);
            mma_f16(sB[0], qaB[3][0], qaB[3][1], qaB[3][2], qaB[3][3], kf3.x, kf3.y);
            mma_f16(sB[1], qaB[3][0], qaB[3][1], qaB[3][2], qaB[3][3], kf3.z, kf3.w);

            // causal mask: key = dbase + 16pp + 8j + 2t (+1); rows g,g+8,+16,+24
            {
                const int d = dbase + 16 * pp + 2 * t;
                if (d + 15 > 0) {   // any masking possible in this chunk
                    #pragma unroll
                    for (int j = 0; j < 2; j++) {
                        int k0 = d + 8 * j;
                        if (k0     > g)      sA[j][0] = -1e30f;
                        if (k0 + 1 > g)      sA[j][1] = -1e30f;
                        if (k0     > g + 8)  sA[j][2] = -1e30f;
                        if (k0 + 1 > g + 8)  sA[j][3] = -1e30f;
                        if (k0     > g + 16) sB[j][0] = -1e30f;
                        if (k0 + 1 > g + 16) sB[j][1] = -1e30f;
                        if (k0     > g + 24) sB[j][2] = -1e30f;
                        if (k0 + 1 > g + 24) sB[j][3] = -1e30f;
                    }
                }
            }

            // P = 2^(S')
            #pragma unroll
            for (int j = 0; j < 2; j++) {
                sA[j][0] = ex2f(sA[j][0]); sA[j][1] = ex2f(sA[j][1]);
                sA[j][2] = ex2f(sA[j][2]); sA[j][3] = ex2f(sA[j][3]);
                sB[j][0] = ex2f(sB[j][0]); sB[j][1] = ex2f(sB[j][1]);
                sB[j][2] = ex2f(sB[j][2]); sB[j][3] = ex2f(sB[j][3]);
            }

            uint32_t a0 = packh2(sA[0][0], sA[0][1]);
            uint32_t a1 = packh2(sA[0][2], sA[0][3]);
            uint32_t a2 = packh2(sA[1][0], sA[1][1]);
            uint32_t a3 = packh2(sA[1][2], sA[1][3]);
            uint32_t b0 = packh2(sB[0][0], sB[0][1]);
            uint32_t b1 = packh2(sB[0][2], sB[0][3]);
            uint32_t b2 = packh2(sB[1][0], sB[1][1]);
            uint32_t b3 = packh2(sB[1][2], sB[1][3]);

            mma_f16(lfA, a0, a1, a2, a3, ONES, ONES);
            mma_f16(lfB, b0, b1, b2, b3, ONES, ONES);

            // O += P @ V : V fragment loaded once, used for both halves
            #pragma unroll
            for (int ntp = 0; ntp < 4; ntp++) {
                uint4 f = Vc[(pp * 4 + ntp) * 32 + l];
                mma_f16(oA[2 * ntp],     a0, a1, a2, a3, f.x, f.y);
                mma_f16(oA[2 * ntp + 1], a0, a1, a2, a3, f.z, f.w);
                mma_f16(oB[2 * ntp],     b0, b1, b2, b3, f.x, f.y);
                mma_f16(oB[2 * ntp + 1], b0, b1, b2, b3, f.z, f.w);
            }
        }
    }

    // ---- epilogue: direct from registers ----
    const float lA0 = lfA[0], lA1 = lfA[2];   // rows 32w+g, +8
    const float lB0 = lfB[0], lB1 = lfB[2];   // rows 32w+16+g, +24

    if (ntiles <= KCHUNK) {
        float iA0 = 1.0f / lA0, iA1 = 1.0f / lA1;
        float iB0 = 1.0f / lB0, iB1 = 1.0f / lB1;
        size_t r0 = ((size_t)b * LSEQ + rowA + g) * DKH;
        #pragma unroll
        for (int nt = 0; nt < 8; nt++) {
            int c = nt * 8 + 2 * t;
            *(float2*)&out[r0 + c]            = make_float2(oA[nt][0] * iA0, oA[nt][1] * iA0);
            *(float2*)&out[r0 + 8 * DKH + c]  = make_float2(oA[nt][2] * iA1, oA[nt][3] * iA1);
            *(float2*)&out[r0 + 16 * DKH + c] = make_float2(oB[nt][0] * iB0, oB[nt][1] * iB0);
            *(float2*)&out[r0 + 24 * DKH + c] = make_float2(oB[nt][2] * iB1, oB[nt][3] * iB1);
        }
    } else {
        const int item = (b * NQB3 + Q) * MAXCH + ci;
        float* dst = g_opart + (size_t)item * 16384;
        const int lr = 32 * w + g;
        #pragma unroll
        for (int nt = 0; nt < 8; nt++) {
            int c = nt * 8 + 2 * t;
            *(float2*)&dst[lr * 64 + c]        = make_float2(oA[nt][0], oA[nt][1]);
            *(float2*)&dst[(lr + 8) * 64 + c]  = make_float2(oA[nt][2], oA[nt][3]);
            *(float2*)&dst[(lr + 16) * 64 + c] = make_float2(oB[nt][0], oB[nt][1]);
            *(float2*)&dst[(lr + 24) * 64 + c] = make_float2(oB[nt][2], oB[nt][3]);
        }
        if (t == 0) {
            g_lpart[item * 256 + lr]      = lA0;
            g_lpart[item * 256 + lr + 8]  = lA1;
            g_lpart[item * 256 + lr + 16] = lB0;
            g_lpart[item * 256 + lr + 24] = lB1;
        }
    }
}

// ---------------------------------------------------------------------------
// Attention stage 2: elementwise reduce, Q >= 2 only.
// 229376 threads: id -> (b, Q-2 of 14, row 0..255, c4)
// ---------------------------------------------------------------------------
__global__ __launch_bounds__(256) void attn_reduce_kernel(float* __restrict__ out)
{
    int id = blockIdx.x * 256 + threadIdx.x;   // 229376
    int c4  = id & 15;
    int row = (id >> 4) & 255;
    int rem = id >> 12;                        // 0..55 = b*14 + (Q-2)
    int b   = rem / 14;
    int Q   = 2 + rem % 14;
    int nch = (4 * Q + 4 + KCHUNK - 1) / KCHUNK;   // 2..8
    int base_item = (b * NQB3 + Q) * MAXCH;

    float4 acc = make_float4(0.f, 0.f, 0.f, 0.f);
    float lac = 0.f;
    for (int ci = 0; ci < nch; ci++) {
        const float4 v = *(const float4*)&g_opart[(size_t)(base_item + ci) * 16384 + row * 64 + c4 * 4];
        acc.x += v.x; acc.y += v.y; acc.z += v.z; acc.w += v.w;
        lac += g_lpart[(base_item + ci) * 256 + row];
    }
    float inv = 1.0f / lac;
    acc.x *= inv; acc.y *= inv; acc.z *= inv; acc.w *= inv;
    size_t orow = ((size_t)b * LSEQ + (size_t)Q * 256 + row) * DKH;
    *(float4*)&out[orow + c4 * 4] = acc;
}

// ---------------------------------------------------------------------------
extern "C" void kernel_launch(void* const* d_in, const int* in_sizes, int n_in,
                              void* d_out, int out_size)
{
    const float* Q  = (const float*)d_in[0];
    const float* K  = (const float*)d_in[1];
    const float* V  = (const float*)d_in[2];
    const float* Wq = (const float*)d_in[3];
    const float* bq = (const float*)d_in[4];
    const float* Wk = (const float*)d_in[5];
    const float* bk = (const float*)d_in[6];
    const float* Wv = (const float*)d_in[7];
    const float* bv = (const float*)d_in[8];
    float* out = (float*)d_out;

    cudaFuncSetAttribute(proj3_kernel, cudaFuncAttributeMaxDynamicSharedMemorySize,
                         P3_SMEM_BYTES);
    cudaFuncSetAttribute(attn_part_kernel, cudaFuncAttributeMaxDynamicSharedMemorySize,
                         ATT_SMEM_BYTES);

    wfrag16_kernel<<<96, 256>>>(Wq, Wk, Wv);

    dim3 pg(MROWS / 128, 1, 3);
    proj3_kernel<<<pg, 256, P3_SMEM_BYTES>>>(Q, K, V, bq, bk, bv);

    repack_kernel<<<512, 256>>>();

    dim3 ag(MAXCH, NQB3, BATCH);
    attn_part_kernel<<<ag, 256, ATT_SMEM_BYTES>>>(out);

    attn_reduce_kernel<<<896, 256>>>(out);
}